// round 3
// baseline (speedup 1.0000x reference)
#include <cuda_runtime.h>
#include <cstdint>

#define N_MAX   100000
#define HD      128
#define NHEADS  8

__device__ float g_Q[N_MAX * HD];
__device__ float g_K[N_MAX * HD];
__device__ float g_V[N_MAX * HD];
__device__ float g_Z[N_MAX * NHEADS];

// ---------------------------------------------------------------------------
// tf32 helpers
// ---------------------------------------------------------------------------
__device__ __forceinline__ float tf32_rna(float x) {
    float r;
    asm("cvt.rna.tf32.f32 %0, %1;" : "=f"(r) : "f"(x));
    return r;
}
// Dekker split: x ≈ hi + lo, both exactly representable in tf32.
__device__ __forceinline__ float2 tf32_split(float x) {
    float hi = tf32_rna(x);
    float lo = tf32_rna(x - hi);
    return make_float2(hi, lo);
}

__device__ __forceinline__ void mma_tf32(float c[4],
                                         uint32_t a0, uint32_t a1, uint32_t a2, uint32_t a3,
                                         uint32_t b0, uint32_t b1) {
    asm volatile(
        "mma.sync.aligned.m16n8k8.row.col.f32.tf32.tf32.f32 "
        "{%0,%1,%2,%3}, {%4,%5,%6,%7}, {%8,%9}, {%0,%1,%2,%3};"
        : "+f"(c[0]), "+f"(c[1]), "+f"(c[2]), "+f"(c[3])
        : "r"(a0), "r"(a1), "r"(a2), "r"(a3), "r"(b0), "r"(b1));
}

// ---------------------------------------------------------------------------
// QKV GEMM on tensor cores (tf32 3-pass split ≈ fp32 accuracy).
// Block tile 128x128, 256 threads = 8 warps (4 warpM x 2 warpN),
// warp tile 32x64 = 2 mtiles x 8 ntiles of m16n8k8.
// K=128 processed in two 64-wide chunks staged in smem as (hi,lo) float2.
// Pad strides (68 / 132 float2) -> conflict-free LDS.64 fragment fetches.
// ---------------------------------------------------------------------------
#define SX 68    // xs2 row stride in float2
#define SW 132   // ws2 row stride in float2

__global__ void __launch_bounds__(256)
qkv_gemm_tc(const float* __restrict__ x,
            const float* __restrict__ Wq, const float* __restrict__ bq,
            const float* __restrict__ Wk, const float* __restrict__ bk,
            const float* __restrict__ Wv, const float* __restrict__ bv,
            int n)
{
    const float* W; const float* bias; float* out;
    if (blockIdx.y == 0)      { W = Wq; bias = bq; out = g_Q; }
    else if (blockIdx.y == 1) { W = Wk; bias = bk; out = g_K; }
    else                      { W = Wv; bias = bv; out = g_V; }

    extern __shared__ float2 smem2[];
    float2* xs2 = smem2;              // [128][SX]  rows x kchunk
    float2* ws2 = smem2 + 128 * SX;   // [64][SW]   kchunk x cols

    const int tid   = threadIdx.x;
    const int lane  = tid & 31;
    const int wid   = tid >> 5;
    const int warpM = wid >> 1;       // 0..3
    const int warpN = wid & 1;        // 0..1
    const int g     = lane >> 2;      // groupID
    const int tg    = lane & 3;       // thread-in-group
    const int row0  = blockIdx.x * 128;

    float acc[2][8][4];
    #pragma unroll
    for (int mt = 0; mt < 2; mt++)
        #pragma unroll
        for (int nt = 0; nt < 8; nt++)
            #pragma unroll
            for (int i = 0; i < 4; i++) acc[mt][nt][i] = 0.f;

    #pragma unroll
    for (int kc = 0; kc < 128; kc += 64) {
        // ---- stage x chunk: 128 rows x 64 k, split to (hi,lo) ----
        #pragma unroll
        for (int j = 0; j < 8; j++) {
            int idx = tid + j * 256;          // float4 index in 128x16 grid
            int r   = idx >> 4;
            int k4  = (idx & 15) * 4;
            float4 v = make_float4(0.f, 0.f, 0.f, 0.f);
            int gr = row0 + r;
            if (gr < n) v = *(const float4*)&x[(size_t)gr * 128 + kc + k4];
            float2* p = &xs2[r * SX + k4];
            p[0] = tf32_split(v.x);
            p[1] = tf32_split(v.y);
            p[2] = tf32_split(v.z);
            p[3] = tf32_split(v.w);
        }
        // ---- stage W chunk: 64 k x 128 n, split ----
        #pragma unroll
        for (int j = 0; j < 8; j++) {
            int idx = tid + j * 256;          // float4 index in 64x32 grid
            int kk  = idx >> 5;
            int n4  = (idx & 31) * 4;
            float4 v = *(const float4*)&W[(size_t)(kc + kk) * 128 + n4];
            float2* p = &ws2[kk * SW + n4];
            p[0] = tf32_split(v.x);
            p[1] = tf32_split(v.y);
            p[2] = tf32_split(v.z);
            p[3] = tf32_split(v.w);
        }
        __syncthreads();

        #pragma unroll
        for (int k8 = 0; k8 < 8; k8++) {
            const int kb = k8 * 8;
            // A fragments (hi,lo) for 2 mtiles
            float2 af[2][4];
            #pragma unroll
            for (int mt = 0; mt < 2; mt++) {
                int r = warpM * 32 + mt * 16 + g;
                af[mt][0] = xs2[r * SX + kb + tg];
                af[mt][1] = xs2[(r + 8) * SX + kb + tg];
                af[mt][2] = xs2[r * SX + kb + tg + 4];
                af[mt][3] = xs2[(r + 8) * SX + kb + tg + 4];
            }
            // B fragments (hi,lo) for 8 ntiles
            float2 bf[8][2];
            #pragma unroll
            for (int nt = 0; nt < 8; nt++) {
                int c = warpN * 64 + nt * 8 + g;
                bf[nt][0] = ws2[(kb + tg) * SW + c];
                bf[nt][1] = ws2[(kb + tg + 4) * SW + c];
            }
            #pragma unroll
            for (int mt = 0; mt < 2; mt++) {
                uint32_t ah0 = __float_as_uint(af[mt][0].x);
                uint32_t ah1 = __float_as_uint(af[mt][1].x);
                uint32_t ah2 = __float_as_uint(af[mt][2].x);
                uint32_t ah3 = __float_as_uint(af[mt][3].x);
                uint32_t al0 = __float_as_uint(af[mt][0].y);
                uint32_t al1 = __float_as_uint(af[mt][1].y);
                uint32_t al2 = __float_as_uint(af[mt][2].y);
                uint32_t al3 = __float_as_uint(af[mt][3].y);
                #pragma unroll
                for (int nt = 0; nt < 8; nt++) {
                    uint32_t bh0 = __float_as_uint(bf[nt][0].x);
                    uint32_t bh1 = __float_as_uint(bf[nt][1].x);
                    uint32_t bl0 = __float_as_uint(bf[nt][0].y);
                    uint32_t bl1 = __float_as_uint(bf[nt][1].y);
                    mma_tf32(acc[mt][nt], ah0, ah1, ah2, ah3, bh0, bh1);
                    mma_tf32(acc[mt][nt], ah0, ah1, ah2, ah3, bl0, bl1);
                    mma_tf32(acc[mt][nt], al0, al1, al2, al3, bh0, bh1);
                }
            }
        }
        __syncthreads();
    }

    // ---- epilogue: +bias, store float2 per (mt,nt,rowhalf) ----
    #pragma unroll
    for (int nt = 0; nt < 8; nt++) {
        int col = warpN * 64 + nt * 8 + tg * 2;
        float b0 = __ldg(&bias[col]);
        float b1 = __ldg(&bias[col + 1]);
        #pragma unroll
        for (int mt = 0; mt < 2; mt++) {
            int r = row0 + warpM * 32 + mt * 16 + g;
            if (r < n) {
                float2 o = make_float2(acc[mt][nt][0] + b0, acc[mt][nt][1] + b1);
                *(float2*)&out[(size_t)r * 128 + col] = o;
            }
            if (r + 8 < n) {
                float2 o = make_float2(acc[mt][nt][2] + b0, acc[mt][nt][3] + b1);
                *(float2*)&out[(size_t)(r + 8) * 128 + col] = o;
            }
        }
    }
}

// ---------------------------------------------------------------------------
__global__ void zero_kernel(float* __restrict__ out, int n_out_f4, int n_z_f4)
{
    int i = blockIdx.x * blockDim.x + threadIdx.x;
    float4 z = make_float4(0.f, 0.f, 0.f, 0.f);
    if (i < n_out_f4) ((float4*)out)[i] = z;
    if (i < n_z_f4)   ((float4*)g_Z)[i] = z;
}

// ---------------------------------------------------------------------------
// Edge phase: one warp per edge (edge_index is int32).
// ---------------------------------------------------------------------------
__global__ void __launch_bounds__(256)
edge_kernel(const int* __restrict__ ei, int E, float* __restrict__ out)
{
    int warp = (blockIdx.x * blockDim.x + threadIdx.x) >> 5;
    int lane = threadIdx.x & 31;
    if (warp >= E) return;

    int src = ei[warp];
    int dst = ei[E + warp];

    float4 kv = *(const float4*)&g_K[(size_t)src * 128 + lane * 4];
    float4 qv = *(const float4*)&g_Q[(size_t)dst * 128 + lane * 4];
    float dot = kv.x * qv.x + kv.y * qv.y + kv.z * qv.z + kv.w * qv.w;
    dot += __shfl_xor_sync(0xffffffffu, dot, 1);
    dot += __shfl_xor_sync(0xffffffffu, dot, 2);
    dot *= 0.25f;
    dot = fminf(fmaxf(dot, -5.0f), 5.0f);
    float score = __expf(dot);

    float4 vv = *(const float4*)&g_V[(size_t)src * 128 + lane * 4];
    float mx = vv.x * score, my = vv.y * score, mz = vv.z * score, mw = vv.w * score;

    float* p = &out[(size_t)dst * 128 + lane * 4];
    asm volatile("red.global.add.v4.f32 [%0], {%1, %2, %3, %4};"
                 :: "l"(p), "f"(mx), "f"(my), "f"(mz), "f"(mw) : "memory");

    if ((lane & 3) == 0)
        atomicAdd(&g_Z[(size_t)dst * NHEADS + (lane >> 2)], score);
}

// ---------------------------------------------------------------------------
__global__ void norm_kernel(float* __restrict__ out, int n)
{
    int i = blockIdx.x * blockDim.x + threadIdx.x;
    if (i >= n * 32) return;
    int node = i >> 5;
    int head = (i & 31) >> 2;
    float z = g_Z[node * NHEADS + head];
    float s = 1.0f / (z + 1e-6f);
    float4 v = ((float4*)out)[i];
    v.x *= s; v.y *= s; v.z *= s; v.w *= s;
    ((float4*)out)[i] = v;
}

// ---------------------------------------------------------------------------
extern "C" void kernel_launch(void* const* d_in, const int* in_sizes, int n_in,
                              void* d_out, int out_size)
{
    const float* x  = (const float*)d_in[0];
    const int*   ei = (const int*)d_in[1];   // int32
    const float* Wq = (const float*)d_in[4];
    const float* bq = (const float*)d_in[5];
    const float* Wk = (const float*)d_in[6];
    const float* bk = (const float*)d_in[7];
    const float* Wv = (const float*)d_in[8];
    const float* bv = (const float*)d_in[9];
    float* out = (float*)d_out;

    int n = in_sizes[0] / 128;
    int E = in_sizes[1] / 2;

    const int smem_bytes = (128 * SX + 64 * SW) * sizeof(float2);  // 137216 B
    cudaFuncSetAttribute(qkv_gemm_tc, cudaFuncAttributeMaxDynamicSharedMemorySize,
                         smem_bytes);

    dim3 gemm_grid((n + 127) / 128, 3);
    qkv_gemm_tc<<<gemm_grid, 256, smem_bytes>>>(x, Wq, bq, Wk, bk, Wv, bv, n);

    int n_out_f4 = n * 32;
    int n_z_f4   = n * 2;
    zero_kernel<<<(n_out_f4 + 255) / 256, 256>>>(out, n_out_f4, n_z_f4);

    edge_kernel<<<(E * 32 + 255) / 256, 256>>>(ei, E, out);

    norm_kernel<<<(n_out_f4 + 255) / 256, 256>>>(out, n);
}

// round 4
// speedup vs baseline: 1.1585x; 1.1585x over previous
#include <cuda_runtime.h>
#include <cstdint>

#define N_MAX   100000
#define E_MAX   800000
#define HD      128
#define NHEADS  8

// Scratch (__device__ globals per allocation rules)
__device__ float g_Q[N_MAX * HD];
__device__ float g_K[N_MAX * HD];
__device__ float g_V[N_MAX * HD];
__device__ int   g_cnt[N_MAX];
__device__ int   g_off[N_MAX + 1];
__device__ int   g_pos[N_MAX];
__device__ int   g_srcs[E_MAX];
__device__ int   g_bsum[256];

// ---------------------------------------------------------------------------
// tf32 helpers (3-product Dekker split: ~fp32 accuracy on tensor cores)
// ---------------------------------------------------------------------------
__device__ __forceinline__ float tf32_rna(float x) {
    float r;
    asm("cvt.rna.tf32.f32 %0, %1;" : "=f"(r) : "f"(x));
    return r;
}
__device__ __forceinline__ float2 tf32_split(float x) {
    float hi = tf32_rna(x);
    float lo = tf32_rna(x - hi);
    return make_float2(hi, lo);
}
__device__ __forceinline__ void mma_tf32(float c[4],
                                         uint32_t a0, uint32_t a1, uint32_t a2, uint32_t a3,
                                         uint32_t b0, uint32_t b1) {
    asm volatile(
        "mma.sync.aligned.m16n8k8.row.col.f32.tf32.tf32.f32 "
        "{%0,%1,%2,%3}, {%4,%5,%6,%7}, {%8,%9}, {%0,%1,%2,%3};"
        : "+f"(c[0]), "+f"(c[1]), "+f"(c[2]), "+f"(c[3])
        : "r"(a0), "r"(a1), "r"(a2), "r"(a3), "r"(b0), "r"(b1));
}

// ---------------------------------------------------------------------------
// QKV GEMM: block tile 64x128, 256 thr = 8 warps (2 warpM x 4 warpN),
// warp tile 32x32 (2 mtiles x 4 ntiles of m16n8k8), K in 4 chunks of 32.
// smem 52 KB -> 2 CTAs/SM. Pad strides SX=36/SW=132 f2 -> conflict-free LDS.64.
// ---------------------------------------------------------------------------
#define SX 36
#define SW 132

__global__ void __launch_bounds__(256, 2)
qkv_gemm_tc(const float* __restrict__ x,
            const float* __restrict__ Wq, const float* __restrict__ bq,
            const float* __restrict__ Wk, const float* __restrict__ bk,
            const float* __restrict__ Wv, const float* __restrict__ bv,
            int n)
{
    const float* W; const float* bias; float* out;
    if (blockIdx.y == 0)      { W = Wq; bias = bq; out = g_Q; }
    else if (blockIdx.y == 1) { W = Wk; bias = bk; out = g_K; }
    else                      { W = Wv; bias = bv; out = g_V; }

    extern __shared__ float2 smem2[];
    float2* xs2 = smem2;             // [64][SX]  rows x kchunk(32)
    float2* ws2 = smem2 + 64 * SX;   // [32][SW]  kchunk x cols(128)

    const int tid   = threadIdx.x;
    const int lane  = tid & 31;
    const int wid   = tid >> 5;
    const int warpM = wid >> 2;      // 0..1
    const int warpN = wid & 3;       // 0..3
    const int g     = lane >> 2;     // 0..7
    const int tg    = lane & 3;      // 0..3
    const int row0  = blockIdx.x * 64;

    float acc[2][4][4];
    #pragma unroll
    for (int mt = 0; mt < 2; mt++)
        #pragma unroll
        for (int nt = 0; nt < 4; nt++)
            #pragma unroll
            for (int i = 0; i < 4; i++) acc[mt][nt][i] = 0.f;

    #pragma unroll
    for (int kc = 0; kc < 128; kc += 32) {
        // stage x: 64 rows x 32 k -> split (hi,lo). 512 float4 / 256 thr = 2 each.
        #pragma unroll
        for (int j = 0; j < 2; j++) {
            int idx = tid + j * 256;
            int r   = idx >> 3;
            int k4  = (idx & 7) * 4;
            float4 v = make_float4(0.f, 0.f, 0.f, 0.f);
            int gr = row0 + r;
            if (gr < n) v = *(const float4*)&x[(size_t)gr * 128 + kc + k4];
            float2* p = &xs2[r * SX + k4];
            p[0] = tf32_split(v.x);
            p[1] = tf32_split(v.y);
            p[2] = tf32_split(v.z);
            p[3] = tf32_split(v.w);
        }
        // stage W: 32 k x 128 n. 1024 float4 / 256 thr = 4 each.
        #pragma unroll
        for (int j = 0; j < 4; j++) {
            int idx = tid + j * 256;
            int kk  = idx >> 5;
            int n4  = (idx & 31) * 4;
            float4 v = *(const float4*)&W[(size_t)(kc + kk) * 128 + n4];
            float2* p = &ws2[kk * SW + n4];
            p[0] = tf32_split(v.x);
            p[1] = tf32_split(v.y);
            p[2] = tf32_split(v.z);
            p[3] = tf32_split(v.w);
        }
        __syncthreads();

        #pragma unroll
        for (int k8 = 0; k8 < 4; k8++) {
            const int kb = k8 * 8;
            float2 af[2][4];
            #pragma unroll
            for (int mt = 0; mt < 2; mt++) {
                int r = warpM * 32 + mt * 16 + g;
                af[mt][0] = xs2[r * SX + kb + tg];
                af[mt][1] = xs2[(r + 8) * SX + kb + tg];
                af[mt][2] = xs2[r * SX + kb + tg + 4];
                af[mt][3] = xs2[(r + 8) * SX + kb + tg + 4];
            }
            float2 bf[4][2];
            #pragma unroll
            for (int nt = 0; nt < 4; nt++) {
                int c = warpN * 32 + nt * 8 + g;
                bf[nt][0] = ws2[(kb + tg) * SW + c];
                bf[nt][1] = ws2[(kb + tg + 4) * SW + c];
            }
            #pragma unroll
            for (int mt = 0; mt < 2; mt++) {
                uint32_t ah0 = __float_as_uint(af[mt][0].x);
                uint32_t ah1 = __float_as_uint(af[mt][1].x);
                uint32_t ah2 = __float_as_uint(af[mt][2].x);
                uint32_t ah3 = __float_as_uint(af[mt][3].x);
                uint32_t al0 = __float_as_uint(af[mt][0].y);
                uint32_t al1 = __float_as_uint(af[mt][1].y);
                uint32_t al2 = __float_as_uint(af[mt][2].y);
                uint32_t al3 = __float_as_uint(af[mt][3].y);
                #pragma unroll
                for (int nt = 0; nt < 4; nt++) {
                    uint32_t bh0 = __float_as_uint(bf[nt][0].x);
                    uint32_t bh1 = __float_as_uint(bf[nt][1].x);
                    uint32_t bl0 = __float_as_uint(bf[nt][0].y);
                    uint32_t bl1 = __float_as_uint(bf[nt][1].y);
                    mma_tf32(acc[mt][nt], ah0, ah1, ah2, ah3, bh0, bh1);
                    mma_tf32(acc[mt][nt], ah0, ah1, ah2, ah3, bl0, bl1);
                    mma_tf32(acc[mt][nt], al0, al1, al2, al3, bh0, bh1);
                }
            }
        }
        __syncthreads();
    }

    #pragma unroll
    for (int nt = 0; nt < 4; nt++) {
        int col = warpN * 32 + nt * 8 + tg * 2;
        float b0 = __ldg(&bias[col]);
        float b1 = __ldg(&bias[col + 1]);
        #pragma unroll
        for (int mt = 0; mt < 2; mt++) {
            int r = row0 + warpM * 32 + mt * 16 + g;
            if (r < n) {
                float2 o = make_float2(acc[mt][nt][0] + b0, acc[mt][nt][1] + b1);
                *(float2*)&out[(size_t)r * 128 + col] = o;
            }
            if (r + 8 < n) {
                float2 o = make_float2(acc[mt][nt][2] + b0, acc[mt][nt][3] + b1);
                *(float2*)&out[(size_t)(r + 8) * 128 + col] = o;
            }
        }
    }
}

// ---------------------------------------------------------------------------
// Counting sort of edges by dst
// ---------------------------------------------------------------------------
__global__ void zero_cnt(int n)
{
    int i = blockIdx.x * blockDim.x + threadIdx.x;
    if (i < n) g_cnt[i] = 0;
}

__global__ void hist_kernel(const int* __restrict__ ei, int E)
{
    int i = blockIdx.x * blockDim.x + threadIdx.x;
    if (i < E) atomicAdd(&g_cnt[ei[E + i]], 1);
}

// Pass 1: per-block sums of 1024 counters
__global__ void scan_pass1(int n)
{
    __shared__ int s[256];
    int b   = blockIdx.x;
    int t   = threadIdx.x;
    int idx = b * 1024 + t * 4;
    int sum = 0;
    #pragma unroll
    for (int k = 0; k < 4; k++)
        if (idx + k < n) sum += g_cnt[idx + k];
    s[t] = sum;
    __syncthreads();
    for (int o = 128; o > 0; o >>= 1) {
        if (t < o) s[t] += s[t + o];
        __syncthreads();
    }
    if (t == 0) g_bsum[b] = s[0];
}

// Pass 2: serial exclusive scan of block sums (nb <= 256, trivial work)
__global__ void scan_pass2(int nb)
{
    if (threadIdx.x == 0 && blockIdx.x == 0) {
        int run = 0;
        for (int b = 0; b < nb; b++) {
            int t = g_bsum[b];
            g_bsum[b] = run;
            run += t;
        }
    }
}

// Pass 3: block-local exclusive scan + base; writes g_off and g_pos
__global__ void scan_pass3(int n, int E)
{
    __shared__ int s[256];
    int b   = blockIdx.x;
    int t   = threadIdx.x;
    int idx = b * 1024 + t * 4;
    int v[4];
    int sum = 0;
    #pragma unroll
    for (int k = 0; k < 4; k++) {
        v[k] = (idx + k < n) ? g_cnt[idx + k] : 0;
        sum += v[k];
    }
    s[t] = sum;
    __syncthreads();
    #pragma unroll
    for (int o = 1; o < 256; o <<= 1) {
        int add = (t >= o) ? s[t - o] : 0;
        __syncthreads();
        s[t] += add;
        __syncthreads();
    }
    int base = g_bsum[b] + s[t] - sum;   // exclusive prefix for this thread
    #pragma unroll
    for (int k = 0; k < 4; k++) {
        if (idx + k < n) {
            g_off[idx + k] = base;
            g_pos[idx + k] = base;
        }
        base += v[k];
    }
    if (b == 0 && t == 0) g_off[n] = E;
}

__global__ void scatter_kernel(const int* __restrict__ ei, int E)
{
    int i = blockIdx.x * blockDim.x + threadIdx.x;
    if (i >= E) return;
    int src = ei[i];
    int dst = ei[E + i];
    int p = atomicAdd(&g_pos[dst], 1);
    g_srcs[p] = src;
}

// ---------------------------------------------------------------------------
// Segmented gather: 1 warp per dst node. Q loaded once; per edge read
// K[src], V[src]; accumulate wV and Z in registers; write normalized output.
// lane l owns dims [4l,4l+3]; quad (lane>>2) = one 16-dim head.
// ---------------------------------------------------------------------------
__global__ void __launch_bounds__(256)
gather_kernel(float* __restrict__ out, int n)
{
    int node = (blockIdx.x * blockDim.x + threadIdx.x) >> 5;
    int lane = threadIdx.x & 31;
    if (node >= n) return;

    int beg = g_off[node];
    int end = g_off[node + 1];

    float4 q = *(const float4*)&g_Q[(size_t)node * 128 + lane * 4];

    float ax = 0.f, ay = 0.f, az = 0.f, aw = 0.f;
    float z = 0.f;

    for (int j = beg; j < end; ++j) {
        int src = g_srcs[j];
        float4 kv = *(const float4*)&g_K[(size_t)src * 128 + lane * 4];
        float dot = kv.x * q.x + kv.y * q.y + kv.z * q.z + kv.w * q.w;
        dot += __shfl_xor_sync(0xffffffffu, dot, 1);
        dot += __shfl_xor_sync(0xffffffffu, dot, 2);
        dot *= 0.25f;                               // 1/sqrt(16)
        dot = fminf(fmaxf(dot, -5.0f), 5.0f);
        float score = __expf(dot);

        float4 vv = *(const float4*)&g_V[(size_t)src * 128 + lane * 4];
        ax += score * vv.x;
        ay += score * vv.y;
        az += score * vv.z;
        aw += score * vv.w;
        z  += score;
    }

    float s = 1.0f / (z + 1e-6f);
    float4 o = make_float4(ax * s, ay * s, az * s, aw * s);
    *(float4*)&out[(size_t)node * 128 + lane * 4] = o;
}

// ---------------------------------------------------------------------------
extern "C" void kernel_launch(void* const* d_in, const int* in_sizes, int n_in,
                              void* d_out, int out_size)
{
    const float* x  = (const float*)d_in[0];
    const int*   ei = (const int*)d_in[1];   // int32 (JAX x64 disabled)
    const float* Wq = (const float*)d_in[4];
    const float* bq = (const float*)d_in[5];
    const float* Wk = (const float*)d_in[6];
    const float* bk = (const float*)d_in[7];
    const float* Wv = (const float*)d_in[8];
    const float* bv = (const float*)d_in[9];
    float* out = (float*)d_out;

    int n = in_sizes[0] / 128;
    int E = in_sizes[1] / 2;

    // --- QKV GEMM (tensor cores, tf32 split) ---
    const int smem_bytes = (64 * SX + 32 * SW) * sizeof(float2);  // 52224 B
    cudaFuncSetAttribute(qkv_gemm_tc, cudaFuncAttributeMaxDynamicSharedMemorySize,
                         smem_bytes);
    dim3 gemm_grid((n + 63) / 64, 3);
    qkv_gemm_tc<<<gemm_grid, 256, smem_bytes>>>(x, Wq, bq, Wk, bk, Wv, bv, n);

    // --- counting sort of edges by dst ---
    int nb = (n + 1023) / 1024;
    zero_cnt<<<(n + 255) / 256, 256>>>(n);
    hist_kernel<<<(E + 255) / 256, 256>>>(ei, E);
    scan_pass1<<<nb, 256>>>(n);
    scan_pass2<<<1, 32>>>(nb);
    scan_pass3<<<nb, 256>>>(n, E);
    scatter_kernel<<<(E + 255) / 256, 256>>>(ei, E);

    // --- segmented attention gather (fused normalize) ---
    gather_kernel<<<(n * 32 + 255) / 256, 256>>>(out, n);
}

// round 5
// speedup vs baseline: 1.4313x; 1.2355x over previous
#include <cuda_runtime.h>
#include <cuda_fp16.h>
#include <cstdint>

#define N_MAX   100000
#define E_MAX   800000
#define HD      128
#define NHEADS  8

// Scratch (__device__ globals per allocation rules)
__device__ float  g_Q[N_MAX * HD];
__device__ __half g_KV[N_MAX * 256];   // per node: 32 groups of {K[4],V[4]} fp16
__device__ int    g_cnt[N_MAX];
__device__ int    g_off[N_MAX + 1];
__device__ int    g_pos[N_MAX];
__device__ int    g_srcs[E_MAX];
__device__ int    g_bsum[256];

// ---------------------------------------------------------------------------
// tf32 helpers
// ---------------------------------------------------------------------------
__device__ __forceinline__ float tf32_rna(float x) {
    float r;
    asm("cvt.rna.tf32.f32 %0, %1;" : "=f"(r) : "f"(x));
    return r;
}
__device__ __forceinline__ float2 tf32_split(float x) {
    float hi = tf32_rna(x);
    float lo = tf32_rna(x - hi);
    return make_float2(hi, lo);
}
__device__ __forceinline__ void mma_tf32(float c[4],
                                         uint32_t a0, uint32_t a1, uint32_t a2, uint32_t a3,
                                         uint32_t b0, uint32_t b1) {
    asm volatile(
        "mma.sync.aligned.m16n8k8.row.col.f32.tf32.tf32.f32 "
        "{%0,%1,%2,%3}, {%4,%5,%6,%7}, {%8,%9}, {%0,%1,%2,%3};"
        : "+f"(c[0]), "+f"(c[1]), "+f"(c[2]), "+f"(c[3])
        : "r"(a0), "r"(a1), "r"(a2), "r"(a3), "r"(b0), "r"(b1));
}

// ---------------------------------------------------------------------------
// QKV GEMM: block tile 64x128, 8 warps (2 warpM x 4 warpN), warp tile 32x32,
// K in 4 chunks of 32. blockIdx.y: 0=Q (1 MMA, fp32 out), 1=K (1 MMA, fp16),
// 2=V (3-MMA split, fp16). smem 52 KB -> 2 CTAs/SM.
// ---------------------------------------------------------------------------
#define SX 36
#define SW 132

__global__ void __launch_bounds__(256, 2)
qkv_gemm_tc(const float* __restrict__ x,
            const float* __restrict__ Wq, const float* __restrict__ bq,
            const float* __restrict__ Wk, const float* __restrict__ bk,
            const float* __restrict__ Wv, const float* __restrict__ bv,
            int n)
{
    const int mode = blockIdx.y;           // 0=Q 1=K 2=V
    const float* W; const float* bias;
    if (mode == 0)      { W = Wq; bias = bq; }
    else if (mode == 1) { W = Wk; bias = bk; }
    else                { W = Wv; bias = bv; }

    extern __shared__ float2 smem2[];
    float2* xs2 = smem2;             // [64][SX]
    float2* ws2 = smem2 + 64 * SX;   // [32][SW]

    const int tid   = threadIdx.x;
    const int lane  = tid & 31;
    const int wid   = tid >> 5;
    const int warpM = wid >> 2;
    const int warpN = wid & 3;
    const int g     = lane >> 2;
    const int tg    = lane & 3;
    const int row0  = blockIdx.x * 64;

    float acc[2][4][4];
    #pragma unroll
    for (int mt = 0; mt < 2; mt++)
        #pragma unroll
        for (int nt = 0; nt < 4; nt++)
            #pragma unroll
            for (int i = 0; i < 4; i++) acc[mt][nt][i] = 0.f;

    #pragma unroll
    for (int kc = 0; kc < 128; kc += 32) {
        #pragma unroll
        for (int j = 0; j < 2; j++) {
            int idx = tid + j * 256;
            int r   = idx >> 3;
            int k4  = (idx & 7) * 4;
            float4 v = make_float4(0.f, 0.f, 0.f, 0.f);
            int gr = row0 + r;
            if (gr < n) v = *(const float4*)&x[(size_t)gr * 128 + kc + k4];
            float2* p = &xs2[r * SX + k4];
            p[0] = tf32_split(v.x);
            p[1] = tf32_split(v.y);
            p[2] = tf32_split(v.z);
            p[3] = tf32_split(v.w);
        }
        #pragma unroll
        for (int j = 0; j < 4; j++) {
            int idx = tid + j * 256;
            int kk  = idx >> 5;
            int n4  = (idx & 31) * 4;
            float4 v = *(const float4*)&W[(size_t)(kc + kk) * 128 + n4];
            float2* p = &ws2[kk * SW + n4];
            p[0] = tf32_split(v.x);
            p[1] = tf32_split(v.y);
            p[2] = tf32_split(v.z);
            p[3] = tf32_split(v.w);
        }
        __syncthreads();

        #pragma unroll
        for (int k8 = 0; k8 < 4; k8++) {
            const int kb = k8 * 8;
            float2 af[2][4];
            #pragma unroll
            for (int mt = 0; mt < 2; mt++) {
                int r = warpM * 32 + mt * 16 + g;
                af[mt][0] = xs2[r * SX + kb + tg];
                af[mt][1] = xs2[(r + 8) * SX + kb + tg];
                af[mt][2] = xs2[r * SX + kb + tg + 4];
                af[mt][3] = xs2[(r + 8) * SX + kb + tg + 4];
            }
            float2 bf[4][2];
            #pragma unroll
            for (int nt = 0; nt < 4; nt++) {
                int c = warpN * 32 + nt * 8 + g;
                bf[nt][0] = ws2[(kb + tg) * SW + c];
                bf[nt][1] = ws2[(kb + tg + 4) * SW + c];
            }
            #pragma unroll
            for (int mt = 0; mt < 2; mt++) {
                uint32_t ah0 = __float_as_uint(af[mt][0].x);
                uint32_t ah1 = __float_as_uint(af[mt][1].x);
                uint32_t ah2 = __float_as_uint(af[mt][2].x);
                uint32_t ah3 = __float_as_uint(af[mt][3].x);
                #pragma unroll
                for (int nt = 0; nt < 4; nt++) {
                    uint32_t bh0 = __float_as_uint(bf[nt][0].x);
                    uint32_t bh1 = __float_as_uint(bf[nt][1].x);
                    mma_tf32(acc[mt][nt], ah0, ah1, ah2, ah3, bh0, bh1);
                    if (mode == 2) {   // V: full-precision 3-product split
                        uint32_t al0 = __float_as_uint(af[mt][0].y);
                        uint32_t al1 = __float_as_uint(af[mt][1].y);
                        uint32_t al2 = __float_as_uint(af[mt][2].y);
                        uint32_t al3 = __float_as_uint(af[mt][3].y);
                        uint32_t bl0 = __float_as_uint(bf[nt][0].y);
                        uint32_t bl1 = __float_as_uint(bf[nt][1].y);
                        mma_tf32(acc[mt][nt], ah0, ah1, ah2, ah3, bl0, bl1);
                        mma_tf32(acc[mt][nt], al0, al1, al2, al3, bh0, bh1);
                    }
                }
            }
        }
        __syncthreads();
    }

    // Epilogue: +bias; Q -> fp32 g_Q; K/V -> fp16 interleaved g_KV.
    #pragma unroll
    for (int nt = 0; nt < 4; nt++) {
        int col = warpN * 32 + nt * 8 + tg * 2;
        float b0 = __ldg(&bias[col]);
        float b1 = __ldg(&bias[col + 1]);
        int grp = col >> 2;
        int off = col & 3;                 // 0 or 2
        int kvslot = (mode == 1) ? 0 : 4;  // K first half, V second half
        #pragma unroll
        for (int mt = 0; mt < 2; mt++) {
            #pragma unroll
            for (int half = 0; half < 2; half++) {
                int r = row0 + warpM * 32 + mt * 16 + g + half * 8;
                if (r >= n) continue;
                float o0 = acc[mt][nt][half * 2 + 0] + b0;
                float o1 = acc[mt][nt][half * 2 + 1] + b1;
                if (mode == 0) {
                    *(float2*)&g_Q[(size_t)r * 128 + col] = make_float2(o0, o1);
                } else {
                    size_t hidx = (size_t)r * 256 + grp * 8 + kvslot + off;
                    *(__half2*)&g_KV[hidx] = __float22half2_rn(make_float2(o0, o1));
                }
            }
        }
    }
}

// ---------------------------------------------------------------------------
// Counting sort of edges by dst
// ---------------------------------------------------------------------------
__global__ void zero_cnt(int n)
{
    int i = blockIdx.x * blockDim.x + threadIdx.x;
    if (i < n) g_cnt[i] = 0;
}

__global__ void hist_kernel(const int* __restrict__ ei, int E)
{
    int i = blockIdx.x * blockDim.x + threadIdx.x;
    if (i < E) atomicAdd(&g_cnt[ei[E + i]], 1);
}

__global__ void scan_pass1(int n)
{
    __shared__ int s[256];
    int b   = blockIdx.x;
    int t   = threadIdx.x;
    int idx = b * 1024 + t * 4;
    int sum = 0;
    #pragma unroll
    for (int k = 0; k < 4; k++)
        if (idx + k < n) sum += g_cnt[idx + k];
    s[t] = sum;
    __syncthreads();
    for (int o = 128; o > 0; o >>= 1) {
        if (t < o) s[t] += s[t + o];
        __syncthreads();
    }
    if (t == 0) g_bsum[b] = s[0];
}

__global__ void scan_pass2(int nb)
{
    if (threadIdx.x == 0 && blockIdx.x == 0) {
        int run = 0;
        for (int b = 0; b < nb; b++) {
            int t = g_bsum[b];
            g_bsum[b] = run;
            run += t;
        }
    }
}

__global__ void scan_pass3(int n, int E)
{
    __shared__ int s[256];
    int b   = blockIdx.x;
    int t   = threadIdx.x;
    int idx = b * 1024 + t * 4;
    int v[4];
    int sum = 0;
    #pragma unroll
    for (int k = 0; k < 4; k++) {
        v[k] = (idx + k < n) ? g_cnt[idx + k] : 0;
        sum += v[k];
    }
    s[t] = sum;
    __syncthreads();
    #pragma unroll
    for (int o = 1; o < 256; o <<= 1) {
        int add = (t >= o) ? s[t - o] : 0;
        __syncthreads();
        s[t] += add;
        __syncthreads();
    }
    int base = g_bsum[b] + s[t] - sum;
    #pragma unroll
    for (int k = 0; k < 4; k++) {
        if (idx + k < n) {
            g_off[idx + k] = base;
            g_pos[idx + k] = base;
        }
        base += v[k];
    }
    if (b == 0 && t == 0) g_off[n] = E;
}

__global__ void scatter_kernel(const int* __restrict__ ei, int E)
{
    int i = blockIdx.x * blockDim.x + threadIdx.x;
    if (i >= E) return;
    int src = ei[i];
    int dst = ei[E + i];
    int p = atomicAdd(&g_pos[dst], 1);
    g_srcs[p] = src;
}

// ---------------------------------------------------------------------------
// Segmented gather: 1 warp per dst node. One 16B load per lane per edge
// (fp16 K+V interleaved). Q fp32 loaded once. Normalized output written once.
// ---------------------------------------------------------------------------
__global__ void __launch_bounds__(256)
gather_kernel(float* __restrict__ out, int n)
{
    int node = (blockIdx.x * blockDim.x + threadIdx.x) >> 5;
    int lane = threadIdx.x & 31;
    if (node >= n) return;

    int beg = g_off[node];
    int end = g_off[node + 1];

    float4 q = *(const float4*)&g_Q[(size_t)node * 128 + lane * 4];

    float ax = 0.f, ay = 0.f, az = 0.f, aw = 0.f;
    float z = 0.f;

    for (int j = beg; j < end; ++j) {
        int src = __ldg(&g_srcs[j]);
        uint4 pk = *(const uint4*)&g_KV[(size_t)src * 256 + lane * 8];
        float2 k0 = __half22float2(*(__half2*)&pk.x);
        float2 k1 = __half22float2(*(__half2*)&pk.y);
        float2 v0 = __half22float2(*(__half2*)&pk.z);
        float2 v1 = __half22float2(*(__half2*)&pk.w);

        float dot = k0.x * q.x + k0.y * q.y + k1.x * q.z + k1.y * q.w;
        dot += __shfl_xor_sync(0xffffffffu, dot, 1);
        dot += __shfl_xor_sync(0xffffffffu, dot, 2);
        dot *= 0.25f;
        dot = fminf(fmaxf(dot, -5.0f), 5.0f);
        float score = __expf(dot);

        ax += score * v0.x;
        ay += score * v0.y;
        az += score * v1.x;
        aw += score * v1.y;
        z  += score;
    }

    float s = 1.0f / (z + 1e-6f);
    *(float4*)&out[(size_t)node * 128 + lane * 4] =
        make_float4(ax * s, ay * s, az * s, aw * s);
}

// ---------------------------------------------------------------------------
extern "C" void kernel_launch(void* const* d_in, const int* in_sizes, int n_in,
                              void* d_out, int out_size)
{
    const float* x  = (const float*)d_in[0];
    const int*   ei = (const int*)d_in[1];   // int32 (JAX x64 disabled)
    const float* Wq = (const float*)d_in[4];
    const float* bq = (const float*)d_in[5];
    const float* Wk = (const float*)d_in[6];
    const float* bk = (const float*)d_in[7];
    const float* Wv = (const float*)d_in[8];
    const float* bv = (const float*)d_in[9];
    float* out = (float*)d_out;

    int n = in_sizes[0] / 128;
    int E = in_sizes[1] / 2;

    const int smem_bytes = (64 * SX + 32 * SW) * sizeof(float2);  // 52224 B
    cudaFuncSetAttribute(qkv_gemm_tc, cudaFuncAttributeMaxDynamicSharedMemorySize,
                         smem_bytes);
    dim3 gemm_grid((n + 63) / 64, 3);
    qkv_gemm_tc<<<gemm_grid, 256, smem_bytes>>>(x, Wq, bq, Wk, bk, Wv, bv, n);

    int nb = (n + 1023) / 1024;
    zero_cnt<<<(n + 255) / 256, 256>>>(n);
    hist_kernel<<<(E + 255) / 256, 256>>>(ei, E);
    scan_pass1<<<nb, 256>>>(n);
    scan_pass2<<<1, 32>>>(nb);
    scan_pass3<<<nb, 256>>>(n, E);
    scatter_kernel<<<(E + 255) / 256, 256>>>(ei, E);

    gather_kernel<<<(n * 32 + 255) / 256, 256>>>(out, n);
}

// round 6
// speedup vs baseline: 1.8410x; 1.2862x over previous
#include <cuda_runtime.h>
#include <cuda_fp16.h>
#include <cstdint>

#define N_MAX   100000
#define E_MAX   800000
#define HD      128
#define NHEADS  8

// Scratch (__device__ globals per allocation rules)
__device__ float  g_Q[N_MAX * HD];
__device__ __half g_KV[N_MAX * 256];   // per node: 32 groups of {K[4],V[4]} fp16
__device__ int    g_cnt[N_MAX];
__device__ int    g_off[N_MAX + 1];
__device__ int    g_pos[N_MAX];
__device__ int    g_srcs[E_MAX];
__device__ int    g_bsum[256];

// ---------------------------------------------------------------------------
// tf32 helpers
// ---------------------------------------------------------------------------
__device__ __forceinline__ float tf32_rna(float x) {
    float r;
    asm("cvt.rna.tf32.f32 %0, %1;" : "=f"(r) : "f"(x));
    return r;
}
__device__ __forceinline__ float2 tf32_split(float x) {
    float hi = tf32_rna(x);
    float lo = tf32_rna(x - hi);
    return make_float2(hi, lo);
}
__device__ __forceinline__ void mma_tf32(float c[4],
                                         uint32_t a0, uint32_t a1, uint32_t a2, uint32_t a3,
                                         uint32_t b0, uint32_t b1) {
    asm volatile(
        "mma.sync.aligned.m16n8k8.row.col.f32.tf32.tf32.f32 "
        "{%0,%1,%2,%3}, {%4,%5,%6,%7}, {%8,%9}, {%0,%1,%2,%3};"
        : "+f"(c[0]), "+f"(c[1]), "+f"(c[2]), "+f"(c[3])
        : "r"(a0), "r"(a1), "r"(a2), "r"(a3), "r"(b0), "r"(b1));
}

// ---------------------------------------------------------------------------
// Q/K GEMM: single tf32 MMA (no split). Block 64x128, warp tile 32x32.
// float smem; SX=36 (bank 4g+tg unique), SW=136 (bank 8tg+g unique).
// blockIdx.y: 0 = Q -> g_Q fp32;  1 = K -> g_KV slot 0 fp16.
// ---------------------------------------------------------------------------
#define QKSX 36
#define QKSW 136

__global__ void __launch_bounds__(256)
qk_gemm_tc(const float* __restrict__ x,
           const float* __restrict__ Wq, const float* __restrict__ bq,
           const float* __restrict__ Wk, const float* __restrict__ bk,
           int n)
{
    const int mode = blockIdx.y;           // 0=Q 1=K
    const float* W    = mode ? Wk : Wq;
    const float* bias = mode ? bk : bq;

    extern __shared__ float smemf[];
    float* xs = smemf;                 // [64][QKSX]
    float* ws = smemf + 64 * QKSX;     // [32][QKSW]

    const int tid   = threadIdx.x;
    const int lane  = tid & 31;
    const int wid   = tid >> 5;
    const int warpM = wid >> 2;
    const int warpN = wid & 3;
    const int g     = lane >> 2;
    const int tg    = lane & 3;
    const int row0  = blockIdx.x * 64;

    float acc[2][4][4];
    #pragma unroll
    for (int mt = 0; mt < 2; mt++)
        #pragma unroll
        for (int nt = 0; nt < 4; nt++)
            #pragma unroll
            for (int i = 0; i < 4; i++) acc[mt][nt][i] = 0.f;

    #pragma unroll
    for (int kc = 0; kc < 128; kc += 32) {
        #pragma unroll
        for (int j = 0; j < 2; j++) {
            int idx = tid + j * 256;
            int r   = idx >> 3;
            int k4  = (idx & 7) * 4;
            float4 v = make_float4(0.f, 0.f, 0.f, 0.f);
            int gr = row0 + r;
            if (gr < n) v = *(const float4*)&x[(size_t)gr * 128 + kc + k4];
            float* p = &xs[r * QKSX + k4];
            p[0] = tf32_rna(v.x);
            p[1] = tf32_rna(v.y);
            p[2] = tf32_rna(v.z);
            p[3] = tf32_rna(v.w);
        }
        #pragma unroll
        for (int j = 0; j < 4; j++) {
            int idx = tid + j * 256;
            int kk  = idx >> 5;
            int n4  = (idx & 31) * 4;
            float4 v = *(const float4*)&W[(size_t)(kc + kk) * 128 + n4];
            float* p = &ws[kk * QKSW + n4];
            p[0] = tf32_rna(v.x);
            p[1] = tf32_rna(v.y);
            p[2] = tf32_rna(v.z);
            p[3] = tf32_rna(v.w);
        }
        __syncthreads();

        #pragma unroll
        for (int k8 = 0; k8 < 4; k8++) {
            const int kb = k8 * 8;
            float af[2][4];
            #pragma unroll
            for (int mt = 0; mt < 2; mt++) {
                int r = warpM * 32 + mt * 16 + g;
                af[mt][0] = xs[r * QKSX + kb + tg];
                af[mt][1] = xs[(r + 8) * QKSX + kb + tg];
                af[mt][2] = xs[r * QKSX + kb + tg + 4];
                af[mt][3] = xs[(r + 8) * QKSX + kb + tg + 4];
            }
            float bfr[4][2];
            #pragma unroll
            for (int nt = 0; nt < 4; nt++) {
                int c = warpN * 32 + nt * 8 + g;
                bfr[nt][0] = ws[(kb + tg) * QKSW + c];
                bfr[nt][1] = ws[(kb + tg + 4) * QKSW + c];
            }
            #pragma unroll
            for (int mt = 0; mt < 2; mt++) {
                #pragma unroll
                for (int nt = 0; nt < 4; nt++) {
                    mma_tf32(acc[mt][nt],
                             __float_as_uint(af[mt][0]), __float_as_uint(af[mt][1]),
                             __float_as_uint(af[mt][2]), __float_as_uint(af[mt][3]),
                             __float_as_uint(bfr[nt][0]), __float_as_uint(bfr[nt][1]));
                }
            }
        }
        __syncthreads();
    }

    #pragma unroll
    for (int nt = 0; nt < 4; nt++) {
        int col = warpN * 32 + nt * 8 + tg * 2;
        float b0 = __ldg(&bias[col]);
        float b1 = __ldg(&bias[col + 1]);
        int grp = col >> 2;
        int off = col & 3;
        #pragma unroll
        for (int mt = 0; mt < 2; mt++) {
            #pragma unroll
            for (int half = 0; half < 2; half++) {
                int r = row0 + warpM * 32 + mt * 16 + g + half * 8;
                if (r >= n) continue;
                float o0 = acc[mt][nt][half * 2 + 0] + b0;
                float o1 = acc[mt][nt][half * 2 + 1] + b1;
                if (mode == 0) {
                    *(float2*)&g_Q[(size_t)r * 128 + col] = make_float2(o0, o1);
                } else {
                    size_t hidx = (size_t)r * 256 + grp * 8 + off;   // K slot
                    *(__half2*)&g_KV[hidx] = __float22half2_rn(make_float2(o0, o1));
                }
            }
        }
    }
}

// ---------------------------------------------------------------------------
// V GEMM: 3-MMA Dekker split (fp32-accurate), output fp16 into g_KV slot 4.
// ---------------------------------------------------------------------------
#define SX 36
#define SW 132

__global__ void __launch_bounds__(256, 2)
v_gemm_tc(const float* __restrict__ x,
          const float* __restrict__ Wv, const float* __restrict__ bv,
          int n)
{
    extern __shared__ float2 smem2[];
    float2* xs2 = smem2;             // [64][SX]
    float2* ws2 = smem2 + 64 * SX;   // [32][SW]

    const int tid   = threadIdx.x;
    const int lane  = tid & 31;
    const int wid   = tid >> 5;
    const int warpM = wid >> 2;
    const int warpN = wid & 3;
    const int g     = lane >> 2;
    const int tg    = lane & 3;
    const int row0  = blockIdx.x * 64;

    float acc[2][4][4];
    #pragma unroll
    for (int mt = 0; mt < 2; mt++)
        #pragma unroll
        for (int nt = 0; nt < 4; nt++)
            #pragma unroll
            for (int i = 0; i < 4; i++) acc[mt][nt][i] = 0.f;

    #pragma unroll
    for (int kc = 0; kc < 128; kc += 32) {
        #pragma unroll
        for (int j = 0; j < 2; j++) {
            int idx = tid + j * 256;
            int r   = idx >> 3;
            int k4  = (idx & 7) * 4;
            float4 v = make_float4(0.f, 0.f, 0.f, 0.f);
            int gr = row0 + r;
            if (gr < n) v = *(const float4*)&x[(size_t)gr * 128 + kc + k4];
            float2* p = &xs2[r * SX + k4];
            p[0] = tf32_split(v.x);
            p[1] = tf32_split(v.y);
            p[2] = tf32_split(v.z);
            p[3] = tf32_split(v.w);
        }
        #pragma unroll
        for (int j = 0; j < 4; j++) {
            int idx = tid + j * 256;
            int kk  = idx >> 5;
            int n4  = (idx & 31) * 4;
            float4 v = *(const float4*)&Wv[(size_t)(kc + kk) * 128 + n4];
            float2* p = &ws2[kk * SW + n4];
            p[0] = tf32_split(v.x);
            p[1] = tf32_split(v.y);
            p[2] = tf32_split(v.z);
            p[3] = tf32_split(v.w);
        }
        __syncthreads();

        #pragma unroll
        for (int k8 = 0; k8 < 4; k8++) {
            const int kb = k8 * 8;
            float2 af[2][4];
            #pragma unroll
            for (int mt = 0; mt < 2; mt++) {
                int r = warpM * 32 + mt * 16 + g;
                af[mt][0] = xs2[r * SX + kb + tg];
                af[mt][1] = xs2[(r + 8) * SX + kb + tg];
                af[mt][2] = xs2[r * SX + kb + tg + 4];
                af[mt][3] = xs2[(r + 8) * SX + kb + tg + 4];
            }
            float2 bf[4][2];
            #pragma unroll
            for (int nt = 0; nt < 4; nt++) {
                int c = warpN * 32 + nt * 8 + g;
                bf[nt][0] = ws2[(kb + tg) * SW + c];
                bf[nt][1] = ws2[(kb + tg + 4) * SW + c];
            }
            #pragma unroll
            for (int mt = 0; mt < 2; mt++) {
                uint32_t ah0 = __float_as_uint(af[mt][0].x);
                uint32_t ah1 = __float_as_uint(af[mt][1].x);
                uint32_t ah2 = __float_as_uint(af[mt][2].x);
                uint32_t ah3 = __float_as_uint(af[mt][3].x);
                uint32_t al0 = __float_as_uint(af[mt][0].y);
                uint32_t al1 = __float_as_uint(af[mt][1].y);
                uint32_t al2 = __float_as_uint(af[mt][2].y);
                uint32_t al3 = __float_as_uint(af[mt][3].y);
                #pragma unroll
                for (int nt = 0; nt < 4; nt++) {
                    uint32_t bh0 = __float_as_uint(bf[nt][0].x);
                    uint32_t bh1 = __float_as_uint(bf[nt][1].x);
                    uint32_t bl0 = __float_as_uint(bf[nt][0].y);
                    uint32_t bl1 = __float_as_uint(bf[nt][1].y);
                    mma_tf32(acc[mt][nt], ah0, ah1, ah2, ah3, bh0, bh1);
                    mma_tf32(acc[mt][nt], ah0, ah1, ah2, ah3, bl0, bl1);
                    mma_tf32(acc[mt][nt], al0, al1, al2, al3, bh0, bh1);
                }
            }
        }
        __syncthreads();
    }

    #pragma unroll
    for (int nt = 0; nt < 4; nt++) {
        int col = warpN * 32 + nt * 8 + tg * 2;
        float b0 = __ldg(&bv[col]);
        float b1 = __ldg(&bv[col + 1]);
        int grp = col >> 2;
        int off = col & 3;
        #pragma unroll
        for (int mt = 0; mt < 2; mt++) {
            #pragma unroll
            for (int half = 0; half < 2; half++) {
                int r = row0 + warpM * 32 + mt * 16 + g + half * 8;
                if (r >= n) continue;
                float o0 = acc[mt][nt][half * 2 + 0] + b0;
                float o1 = acc[mt][nt][half * 2 + 1] + b1;
                size_t hidx = (size_t)r * 256 + grp * 8 + 4 + off;   // V slot
                *(__half2*)&g_KV[hidx] = __float22half2_rn(make_float2(o0, o1));
            }
        }
    }
}

// ---------------------------------------------------------------------------
// Counting sort of edges by dst
// ---------------------------------------------------------------------------
__global__ void zero_cnt(int n)
{
    int i = blockIdx.x * blockDim.x + threadIdx.x;
    if (i < n) g_cnt[i] = 0;
}

__global__ void hist_kernel(const int* __restrict__ ei, int E)
{
    int i = blockIdx.x * blockDim.x + threadIdx.x;
    if (i < E) atomicAdd(&g_cnt[ei[E + i]], 1);
}

__global__ void scan_pass1(int n)
{
    __shared__ int s[256];
    int b   = blockIdx.x;
    int t   = threadIdx.x;
    int idx = b * 1024 + t * 4;
    int sum = 0;
    #pragma unroll
    for (int k = 0; k < 4; k++)
        if (idx + k < n) sum += g_cnt[idx + k];
    s[t] = sum;
    __syncthreads();
    for (int o = 128; o > 0; o >>= 1) {
        if (t < o) s[t] += s[t + o];
        __syncthreads();
    }
    if (t == 0) g_bsum[b] = s[0];
}

// Parallel exclusive scan of block sums (nb <= 256)
__global__ void scan_pass2(int nb)
{
    __shared__ int s[256];
    int t = threadIdx.x;
    s[t] = (t < nb) ? g_bsum[t] : 0;
    __syncthreads();
    #pragma unroll
    for (int o = 1; o < 256; o <<= 1) {
        int add = (t >= o) ? s[t - o] : 0;
        __syncthreads();
        s[t] += add;
        __syncthreads();
    }
    if (t < nb) g_bsum[t] = (t == 0) ? 0 : s[t - 1];
}

__global__ void scan_pass3(int n, int E)
{
    __shared__ int s[256];
    int b   = blockIdx.x;
    int t   = threadIdx.x;
    int idx = b * 1024 + t * 4;
    int v[4];
    int sum = 0;
    #pragma unroll
    for (int k = 0; k < 4; k++) {
        v[k] = (idx + k < n) ? g_cnt[idx + k] : 0;
        sum += v[k];
    }
    s[t] = sum;
    __syncthreads();
    #pragma unroll
    for (int o = 1; o < 256; o <<= 1) {
        int add = (t >= o) ? s[t - o] : 0;
        __syncthreads();
        s[t] += add;
        __syncthreads();
    }
    int base = g_bsum[b] + s[t] - sum;
    #pragma unroll
    for (int k = 0; k < 4; k++) {
        if (idx + k < n) {
            g_off[idx + k] = base;
            g_pos[idx + k] = base;
        }
        base += v[k];
    }
    if (b == 0 && t == 0) g_off[n] = E;
}

__global__ void scatter_kernel(const int* __restrict__ ei, int E)
{
    int i = blockIdx.x * blockDim.x + threadIdx.x;
    if (i >= E) return;
    int src = ei[i];
    int dst = ei[E + i];
    int p = atomicAdd(&g_pos[dst], 1);
    g_srcs[p] = src;
}

// ---------------------------------------------------------------------------
// Segmented gather, 4x unrolled for MLP. 1 warp per dst node.
// ---------------------------------------------------------------------------
__device__ __forceinline__ void gather_edge(uint4 pk, float4 q,
                                            float& ax, float& ay, float& az,
                                            float& aw, float& z)
{
    float2 k0 = __half22float2(*(__half2*)&pk.x);
    float2 k1 = __half22float2(*(__half2*)&pk.y);
    float2 v0 = __half22float2(*(__half2*)&pk.z);
    float2 v1 = __half22float2(*(__half2*)&pk.w);

    float dot = k0.x * q.x + k0.y * q.y + k1.x * q.z + k1.y * q.w;
    dot += __shfl_xor_sync(0xffffffffu, dot, 1);
    dot += __shfl_xor_sync(0xffffffffu, dot, 2);
    dot *= 0.25f;
    dot = fminf(fmaxf(dot, -5.0f), 5.0f);
    float score = __expf(dot);

    ax += score * v0.x;
    ay += score * v0.y;
    az += score * v1.x;
    aw += score * v1.y;
    z  += score;
}

__global__ void __launch_bounds__(256)
gather_kernel(float* __restrict__ out, int n)
{
    int node = (blockIdx.x * blockDim.x + threadIdx.x) >> 5;
    int lane = threadIdx.x & 31;
    if (node >= n) return;

    int beg = g_off[node];
    int end = g_off[node + 1];

    float4 q = *(const float4*)&g_Q[(size_t)node * 128 + lane * 4];

    float ax = 0.f, ay = 0.f, az = 0.f, aw = 0.f;
    float z = 0.f;

    int j = beg;
    for (; j + 4 <= end; j += 4) {
        int s0 = __ldg(&g_srcs[j + 0]);
        int s1 = __ldg(&g_srcs[j + 1]);
        int s2 = __ldg(&g_srcs[j + 2]);
        int s3 = __ldg(&g_srcs[j + 3]);
        uint4 p0 = *(const uint4*)&g_KV[(size_t)s0 * 256 + lane * 8];
        uint4 p1 = *(const uint4*)&g_KV[(size_t)s1 * 256 + lane * 8];
        uint4 p2 = *(const uint4*)&g_KV[(size_t)s2 * 256 + lane * 8];
        uint4 p3 = *(const uint4*)&g_KV[(size_t)s3 * 256 + lane * 8];
        gather_edge(p0, q, ax, ay, az, aw, z);
        gather_edge(p1, q, ax, ay, az, aw, z);
        gather_edge(p2, q, ax, ay, az, aw, z);
        gather_edge(p3, q, ax, ay, az, aw, z);
    }
    for (; j < end; ++j) {
        int s0 = __ldg(&g_srcs[j]);
        uint4 p0 = *(const uint4*)&g_KV[(size_t)s0 * 256 + lane * 8];
        gather_edge(p0, q, ax, ay, az, aw, z);
    }

    float s = 1.0f / (z + 1e-6f);
    *(float4*)&out[(size_t)node * 128 + lane * 4] =
        make_float4(ax * s, ay * s, az * s, aw * s);
}

// ---------------------------------------------------------------------------
extern "C" void kernel_launch(void* const* d_in, const int* in_sizes, int n_in,
                              void* d_out, int out_size)
{
    const float* x  = (const float*)d_in[0];
    const int*   ei = (const int*)d_in[1];   // int32 (JAX x64 disabled)
    const float* Wq = (const float*)d_in[4];
    const float* bq = (const float*)d_in[5];
    const float* Wk = (const float*)d_in[6];
    const float* bk = (const float*)d_in[7];
    const float* Wv = (const float*)d_in[8];
    const float* bv = (const float*)d_in[9];
    float* out = (float*)d_out;

    int n = in_sizes[0] / 128;
    int E = in_sizes[1] / 2;

    // --- QK GEMM (single tf32) ---
    const int qk_smem = (64 * QKSX + 32 * QKSW) * sizeof(float);   // 26624 B
    dim3 qk_grid((n + 63) / 64, 2);
    qk_gemm_tc<<<qk_grid, 256, qk_smem>>>(x, Wq, bq, Wk, bk, n);

    // --- V GEMM (split tf32) ---
    const int v_smem = (64 * SX + 32 * SW) * sizeof(float2);       // 52224 B
    cudaFuncSetAttribute(v_gemm_tc, cudaFuncAttributeMaxDynamicSharedMemorySize,
                         v_smem);
    v_gemm_tc<<<(n + 63) / 64, 256, v_smem>>>(x, Wv, bv, n);

    // --- counting sort of edges by dst ---
    int nb = (n + 1023) / 1024;
    zero_cnt<<<(n + 255) / 256, 256>>>(n);
    hist_kernel<<<(E + 255) / 256, 256>>>(ei, E);
    scan_pass1<<<nb, 256>>>(n);
    scan_pass2<<<1, 256>>>(nb);
    scan_pass3<<<nb, 256>>>(n, E);
    scatter_kernel<<<(E + 255) / 256, 256>>>(ei, E);

    // --- segmented attention gather (fused normalize) ---
    gather_kernel<<<(n * 32 + 255) / 256, 256>>>(out, n);
}

// round 7
// speedup vs baseline: 2.1821x; 1.1853x over previous
#include <cuda_runtime.h>
#include <cuda_fp16.h>
#include <cstdint>

#define N_MAX   100000
#define E_MAX   800000
#define HD      128
#define NHEADS  8

// Scratch (__device__ globals per allocation rules)
__device__ float  g_Q[N_MAX * HD];
__device__ __half g_KV[N_MAX * 256];   // per node: 32 groups of {K[4],V[4]} fp16
__device__ int    g_cnt[N_MAX];
__device__ int    g_off[N_MAX + 1];
__device__ int    g_pos[N_MAX];
__device__ int    g_srcs[E_MAX];
__device__ int    g_bsum[256];

// ---------------------------------------------------------------------------
// tf32 helpers
// ---------------------------------------------------------------------------
__device__ __forceinline__ float tf32_rna(float x) {
    float r;
    asm("cvt.rna.tf32.f32 %0, %1;" : "=f"(r) : "f"(x));
    return r;
}
__device__ __forceinline__ void mma_tf32(float c[4],
                                         uint32_t a0, uint32_t a1, uint32_t a2, uint32_t a3,
                                         uint32_t b0, uint32_t b1) {
    asm volatile(
        "mma.sync.aligned.m16n8k8.row.col.f32.tf32.tf32.f32 "
        "{%0,%1,%2,%3}, {%4,%5,%6,%7}, {%8,%9}, {%0,%1,%2,%3};"
        : "+f"(c[0]), "+f"(c[1]), "+f"(c[2]), "+f"(c[3])
        : "r"(a0), "r"(a1), "r"(a2), "r"(a3), "r"(b0), "r"(b1));
}

// ---------------------------------------------------------------------------
// QKV GEMM, single tf32 MMA per k8 (all three projections).
// Block 64x128, 8 warps (2 warpM x 4 warpN), warp tile 32x32, K in 4x32 chunks.
// float smem; SX=36 (banks 4g+tg unique), SW=136 (banks 8tg+g unique).
// blockIdx.y: 0 = Q -> g_Q fp32; 1 = K -> g_KV slot 0; 2 = V -> g_KV slot 4.
// ---------------------------------------------------------------------------
#define QKSX 36
#define QKSW 136

__global__ void __launch_bounds__(256)
qkv_gemm_tc(const float* __restrict__ x,
            const float* __restrict__ Wq, const float* __restrict__ bq,
            const float* __restrict__ Wk, const float* __restrict__ bk,
            const float* __restrict__ Wv, const float* __restrict__ bv,
            int n)
{
    const int mode = blockIdx.y;           // 0=Q 1=K 2=V
    const float* W; const float* bias;
    if (mode == 0)      { W = Wq; bias = bq; }
    else if (mode == 1) { W = Wk; bias = bk; }
    else                { W = Wv; bias = bv; }

    extern __shared__ float smemf[];
    float* xs = smemf;                 // [64][QKSX]
    float* ws = smemf + 64 * QKSX;     // [32][QKSW]

    const int tid   = threadIdx.x;
    const int lane  = tid & 31;
    const int wid   = tid >> 5;
    const int warpM = wid >> 2;
    const int warpN = wid & 3;
    const int g     = lane >> 2;
    const int tg    = lane & 3;
    const int row0  = blockIdx.x * 64;

    float acc[2][4][4];
    #pragma unroll
    for (int mt = 0; mt < 2; mt++)
        #pragma unroll
        for (int nt = 0; nt < 4; nt++)
            #pragma unroll
            for (int i = 0; i < 4; i++) acc[mt][nt][i] = 0.f;

    #pragma unroll
    for (int kc = 0; kc < 128; kc += 32) {
        #pragma unroll
        for (int j = 0; j < 2; j++) {
            int idx = tid + j * 256;
            int r   = idx >> 3;
            int k4  = (idx & 7) * 4;
            float4 v = make_float4(0.f, 0.f, 0.f, 0.f);
            int gr = row0 + r;
            if (gr < n) v = *(const float4*)&x[(size_t)gr * 128 + kc + k4];
            float* p = &xs[r * QKSX + k4];
            p[0] = tf32_rna(v.x);
            p[1] = tf32_rna(v.y);
            p[2] = tf32_rna(v.z);
            p[3] = tf32_rna(v.w);
        }
        #pragma unroll
        for (int j = 0; j < 4; j++) {
            int idx = tid + j * 256;
            int kk  = idx >> 5;
            int n4  = (idx & 31) * 4;
            float4 v = *(const float4*)&W[(size_t)(kc + kk) * 128 + n4];
            float* p = &ws[kk * QKSW + n4];
            p[0] = tf32_rna(v.x);
            p[1] = tf32_rna(v.y);
            p[2] = tf32_rna(v.z);
            p[3] = tf32_rna(v.w);
        }
        __syncthreads();

        #pragma unroll
        for (int k8 = 0; k8 < 4; k8++) {
            const int kb = k8 * 8;
            float af[2][4];
            #pragma unroll
            for (int mt = 0; mt < 2; mt++) {
                int r = warpM * 32 + mt * 16 + g;
                af[mt][0] = xs[r * QKSX + kb + tg];
                af[mt][1] = xs[(r + 8) * QKSX + kb + tg];
                af[mt][2] = xs[r * QKSX + kb + tg + 4];
                af[mt][3] = xs[(r + 8) * QKSX + kb + tg + 4];
            }
            float bfr[4][2];
            #pragma unroll
            for (int nt = 0; nt < 4; nt++) {
                int c = warpN * 32 + nt * 8 + g;
                bfr[nt][0] = ws[(kb + tg) * QKSW + c];
                bfr[nt][1] = ws[(kb + tg + 4) * QKSW + c];
            }
            #pragma unroll
            for (int mt = 0; mt < 2; mt++) {
                #pragma unroll
                for (int nt = 0; nt < 4; nt++) {
                    mma_tf32(acc[mt][nt],
                             __float_as_uint(af[mt][0]), __float_as_uint(af[mt][1]),
                             __float_as_uint(af[mt][2]), __float_as_uint(af[mt][3]),
                             __float_as_uint(bfr[nt][0]), __float_as_uint(bfr[nt][1]));
                }
            }
        }
        __syncthreads();
    }

    #pragma unroll
    for (int nt = 0; nt < 4; nt++) {
        int col = warpN * 32 + nt * 8 + tg * 2;
        float b0 = __ldg(&bias[col]);
        float b1 = __ldg(&bias[col + 1]);
        int grp = col >> 2;
        int off = col & 3;
        int kvslot = (mode == 1) ? 0 : 4;
        #pragma unroll
        for (int mt = 0; mt < 2; mt++) {
            #pragma unroll
            for (int half = 0; half < 2; half++) {
                int r = row0 + warpM * 32 + mt * 16 + g + half * 8;
                if (r >= n) continue;
                float o0 = acc[mt][nt][half * 2 + 0] + b0;
                float o1 = acc[mt][nt][half * 2 + 1] + b1;
                if (mode == 0) {
                    *(float2*)&g_Q[(size_t)r * 128 + col] = make_float2(o0, o1);
                } else {
                    size_t hidx = (size_t)r * 256 + grp * 8 + kvslot + off;
                    *(__half2*)&g_KV[hidx] = __float22half2_rn(make_float2(o0, o1));
                }
            }
        }
    }
}

// ---------------------------------------------------------------------------
// Counting sort of edges by dst
// ---------------------------------------------------------------------------
__global__ void zero_cnt(int n)
{
    int i = blockIdx.x * blockDim.x + threadIdx.x;
    if (i < n) g_cnt[i] = 0;
}

__global__ void hist_kernel(const int* __restrict__ ei, int E)
{
    int i = blockIdx.x * blockDim.x + threadIdx.x;
    if (i < E) atomicAdd(&g_cnt[ei[E + i]], 1);
}

__global__ void scan_pass1(int n)
{
    __shared__ int s[256];
    int b   = blockIdx.x;
    int t   = threadIdx.x;
    int idx = b * 1024 + t * 4;
    int sum = 0;
    #pragma unroll
    for (int k = 0; k < 4; k++)
        if (idx + k < n) sum += g_cnt[idx + k];
    s[t] = sum;
    __syncthreads();
    for (int o = 128; o > 0; o >>= 1) {
        if (t < o) s[t] += s[t + o];
        __syncthreads();
    }
    if (t == 0) g_bsum[b] = s[0];
}

__global__ void scan_pass2(int nb)
{
    __shared__ int s[256];
    int t = threadIdx.x;
    s[t] = (t < nb) ? g_bsum[t] : 0;
    __syncthreads();
    #pragma unroll
    for (int o = 1; o < 256; o <<= 1) {
        int add = (t >= o) ? s[t - o] : 0;
        __syncthreads();
        s[t] += add;
        __syncthreads();
    }
    if (t < nb) g_bsum[t] = (t == 0) ? 0 : s[t - 1];
}

__global__ void scan_pass3(int n, int E)
{
    __shared__ int s[256];
    int b   = blockIdx.x;
    int t   = threadIdx.x;
    int idx = b * 1024 + t * 4;
    int v[4];
    int sum = 0;
    #pragma unroll
    for (int k = 0; k < 4; k++) {
        v[k] = (idx + k < n) ? g_cnt[idx + k] : 0;
        sum += v[k];
    }
    s[t] = sum;
    __syncthreads();
    #pragma unroll
    for (int o = 1; o < 256; o <<= 1) {
        int add = (t >= o) ? s[t - o] : 0;
        __syncthreads();
        s[t] += add;
        __syncthreads();
    }
    int base = g_bsum[b] + s[t] - sum;
    #pragma unroll
    for (int k = 0; k < 4; k++) {
        if (idx + k < n) {
            g_off[idx + k] = base;
            g_pos[idx + k] = base;
        }
        base += v[k];
    }
    if (b == 0 && t == 0) g_off[n] = E;
}

__global__ void scatter_kernel(const int* __restrict__ ei, int E)
{
    int i = blockIdx.x * blockDim.x + threadIdx.x;
    if (i >= E) return;
    int src = ei[i];
    int dst = ei[E + i];
    int p = atomicAdd(&g_pos[dst], 1);
    g_srcs[p] = src;
}

// ---------------------------------------------------------------------------
// Segmented gather: 1 warp per dst node; uniform MLP-4 via clamped predicated
// chunks (guards are warp-uniform -> shfl full-mask safe).
// ---------------------------------------------------------------------------
__device__ __forceinline__ void gather_edge(uint4 pk, float4 q,
                                            float& ax, float& ay, float& az,
                                            float& aw, float& z)
{
    float2 k0 = __half22float2(*(__half2*)&pk.x);
    float2 k1 = __half22float2(*(__half2*)&pk.y);
    float2 v0 = __half22float2(*(__half2*)&pk.z);
    float2 v1 = __half22float2(*(__half2*)&pk.w);

    float dot = k0.x * q.x + k0.y * q.y + k1.x * q.z + k1.y * q.w;
    dot += __shfl_xor_sync(0xffffffffu, dot, 1);
    dot += __shfl_xor_sync(0xffffffffu, dot, 2);
    dot *= 0.25f;
    dot = fminf(fmaxf(dot, -5.0f), 5.0f);
    float score = __expf(dot);

    ax += score * v0.x;
    ay += score * v0.y;
    az += score * v1.x;
    aw += score * v1.y;
    z  += score;
}

__global__ void __launch_bounds__(256)
gather_kernel(float* __restrict__ out, int n)
{
    int node = (blockIdx.x * blockDim.x + threadIdx.x) >> 5;
    int lane = threadIdx.x & 31;
    if (node >= n) return;

    int beg = g_off[node];
    int end = g_off[node + 1];

    float4 q = *(const float4*)&g_Q[(size_t)node * 128 + lane * 4];

    float ax = 0.f, ay = 0.f, az = 0.f, aw = 0.f;
    float z = 0.f;

    int last = end - 1;
    for (int j = beg; j < end; j += 4) {
        int j1 = min(j + 1, last);
        int j2 = min(j + 2, last);
        int j3 = min(j + 3, last);
        int s0 = __ldg(&g_srcs[j]);
        int s1 = __ldg(&g_srcs[j1]);
        int s2 = __ldg(&g_srcs[j2]);
        int s3 = __ldg(&g_srcs[j3]);
        uint4 p0 = *(const uint4*)&g_KV[(size_t)s0 * 256 + lane * 8];
        uint4 p1 = *(const uint4*)&g_KV[(size_t)s1 * 256 + lane * 8];
        uint4 p2 = *(const uint4*)&g_KV[(size_t)s2 * 256 + lane * 8];
        uint4 p3 = *(const uint4*)&g_KV[(size_t)s3 * 256 + lane * 8];
        gather_edge(p0, q, ax, ay, az, aw, z);
        if (j + 1 < end) gather_edge(p1, q, ax, ay, az, aw, z);
        if (j + 2 < end) gather_edge(p2, q, ax, ay, az, aw, z);
        if (j + 3 < end) gather_edge(p3, q, ax, ay, az, aw, z);
    }

    float s = 1.0f / (z + 1e-6f);
    *(float4*)&out[(size_t)node * 128 + lane * 4] =
        make_float4(ax * s, ay * s, az * s, aw * s);
}

// ---------------------------------------------------------------------------
extern "C" void kernel_launch(void* const* d_in, const int* in_sizes, int n_in,
                              void* d_out, int out_size)
{
    const float* x  = (const float*)d_in[0];
    const int*   ei = (const int*)d_in[1];   // int32 (JAX x64 disabled)
    const float* Wq = (const float*)d_in[4];
    const float* bq = (const float*)d_in[5];
    const float* Wk = (const float*)d_in[6];
    const float* bk = (const float*)d_in[7];
    const float* Wv = (const float*)d_in[8];
    const float* bv = (const float*)d_in[9];
    float* out = (float*)d_out;

    int n = in_sizes[0] / 128;
    int E = in_sizes[1] / 2;

    // --- QKV GEMM (single tf32 per projection) ---
    const int smem_bytes = (64 * QKSX + 32 * QKSW) * sizeof(float);  // 26624 B
    dim3 gemm_grid((n + 63) / 64, 3);
    qkv_gemm_tc<<<gemm_grid, 256, smem_bytes>>>(x, Wq, bq, Wk, bk, Wv, bv, n);

    // --- counting sort of edges by dst ---
    int nb = (n + 1023) / 1024;
    zero_cnt<<<(n + 255) / 256, 256>>>(n);
    hist_kernel<<<(E + 255) / 256, 256>>>(ei, E);
    scan_pass1<<<nb, 256>>>(n);
    scan_pass2<<<1, 256>>>(nb);
    scan_pass3<<<nb, 256>>>(n, E);
    scatter_kernel<<<(E + 255) / 256, 256>>>(ei, E);

    // --- segmented attention gather (fused normalize) ---
    gather_kernel<<<(n * 32 + 255) / 256, 256>>>(out, n);
}